// round 16
// baseline (speedup 1.0000x reference)
#include <cuda_runtime.h>
#include <cuda_fp16.h>
#include <cstdint>

#define BATCH 4
#define SEQ   2048
#define DMODEL 1024
#define BS_ROWS (BATCH*SEQ)   // 8192
#define WSZ (DMODEL*DMODEL)

#define BM 128
#define BN 256
#define BKE 128                // fp16 K elems per stage (2 x 128B chunks)
#define NTHREADS 256
#define STAGE_BYTES 98304      // A 32K (2x16K) + B 64K (2x32K)
#define SMEM_TOTAL (1024 + 2*STAGE_BYTES)

// ------------------------- scratch (device globals) -------------------------
__device__ __half g_Xh[BS_ROWS*DMODEL];
__device__ __half g_Wc[4*WSZ];                       // [Wq/32, Wk, Wv, Wo]
__device__ __half g_QKVh[3*(size_t)BS_ROWS*DMODEL];  // [Q/32, K, V] row-major
__device__ __half g_WpT[(size_t)DMODEL*BS_ROWS];     // Wo @ V^T
__device__ __half g_Ph[(size_t)BATCH*SEQ*SEQ];
__device__ __half g_Sh[(size_t)BATCH*SEQ*SEQ];       // scores, fp16
__device__ float  g_bqkv[3*DMODEL];                  // [bq/32, bk, bv]

// ------------------------- PTX helpers -------------------------
__device__ __forceinline__ uint32_t smem_u32(const void* p) {
    uint32_t a;
    asm("{ .reg .u64 t; cvta.to.shared.u64 t, %1; cvt.u32.u64 %0, t; }" : "=r"(a) : "l"(p));
    return a;
}
__device__ __forceinline__ uint32_t swz(uint32_t o) { return o ^ ((o >> 3) & 0x70); }

__device__ __forceinline__ void cp16(uint32_t s, const void* g) {
    asm volatile("cp.async.cg.shared.global [%0], [%1], 16;" :: "r"(s), "l"(g) : "memory");
}
__device__ __forceinline__ void cp_commit() { asm volatile("cp.async.commit_group;" ::: "memory"); }
__device__ __forceinline__ void cp_wait0()  { asm volatile("cp.async.wait_group 0;" ::: "memory"); }
__device__ __forceinline__ void cp_wait1()  { asm volatile("cp.async.wait_group 1;" ::: "memory"); }

__device__ __forceinline__ void ldsm4(uint32_t* r, uint32_t addr) {
    asm volatile("ldmatrix.sync.aligned.m8n8.x4.shared.b16 {%0,%1,%2,%3}, [%4];"
                 : "=r"(r[0]), "=r"(r[1]), "=r"(r[2]), "=r"(r[3]) : "r"(addr));
}
__device__ __forceinline__ void mma_f32acc(float* d, const uint32_t* a, const uint32_t* b) {
    asm volatile(
        "mma.sync.aligned.m16n8k16.row.col.f32.f16.f16.f32 "
        "{%0,%1,%2,%3}, {%4,%5,%6,%7}, {%8,%9}, {%0,%1,%2,%3};"
        : "+f"(d[0]), "+f"(d[1]), "+f"(d[2]), "+f"(d[3])
        : "r"(a[0]), "r"(a[1]), "r"(a[2]), "r"(a[3]), "r"(b[0]), "r"(b[1]));
}
__device__ __forceinline__ void mma_f16acc(uint32_t* d, const uint32_t* a, const uint32_t* b) {
    asm volatile(
        "mma.sync.aligned.m16n8k16.row.col.f16.f16.f16.f16 "
        "{%0,%1}, {%2,%3,%4,%5}, {%6,%7}, {%0,%1};"
        : "+r"(d[0]), "+r"(d[1])
        : "r"(a[0]), "r"(a[1]), "r"(a[2]), "r"(a[3]), "r"(b[0]), "r"(b[1]));
}
__device__ __forceinline__ uint32_t pack_h2(__half a, __half b) {
    __half2 p; p.x = a; p.y = b;
    return *(uint32_t*)&p;
}

// ======================= shared tile machinery =======================
struct TileCtx {
    uint32_t su;
    int tid, lane, warp_m, warp_n;
    int arow, achk, brow, bchk;
};
__device__ __forceinline__ TileCtx tile_ctx(char* smem_raw) {
    TileCtx c;
    c.su = (smem_u32(smem_raw) + 1023u) & ~1023u;
    c.tid = threadIdx.x;
    c.lane = c.tid & 31;
    int wid = c.tid >> 5;
    c.warp_m = wid >> 2;
    c.warp_n = wid & 3;
    c.arow = c.warp_m * 64 + (c.lane & 7) + ((c.lane >> 3) & 1) * 8;
    c.achk = (c.lane >> 4) * 16;
    c.brow = c.warp_n * 64 + (c.lane & 7) + ((c.lane >> 4) & 1) * 8;
    c.bchk = ((c.lane >> 3) & 1) * 16;
    return c;
}
__device__ __forceinline__ void load_stage_g(
    const TileCtx& c, int buf, int kt,
    const __half* __restrict__ A, int lda, const __half* __restrict__ B, int ldb,
    int m0, int n0)
{
    const uint32_t base = c.su + buf * STAGE_BYTES;
    const __half* gA = A + (size_t)m0 * lda + kt;
    const __half* gB = B + (size_t)n0 * ldb + kt;
#pragma unroll
    for (int ch = 0; ch < 2; ch++) {
#pragma unroll
        for (int i = 0; i < 4; i++) {
            int u = c.tid + i * NTHREADS;
            int r = u >> 3, eb = (u & 7) * 16;
            cp16(base + ch * 16384 + swz((uint32_t)(r * 128 + eb)),
                 gA + (size_t)r * lda + (eb >> 1) + ch * 64);
        }
#pragma unroll
        for (int i = 0; i < 8; i++) {
            int u = c.tid + i * NTHREADS;
            int r = u >> 3, eb = (u & 7) * 16;
            cp16(base + 32768 + ch * 32768 + swz((uint32_t)(r * 128 + eb)),
                 gB + (size_t)r * ldb + (eb >> 1) + ch * 64);
        }
    }
    cp_commit();
}
// load current k16 operand fragments
__device__ __forceinline__ void load_frags(
    const TileCtx& c, int buf, int ch, int k16, uint32_t av[4][4], uint32_t bv[8][2])
{
    const uint32_t sb = c.su + buf * STAGE_BYTES;
    const uint32_t aA = sb + ch * 16384;
    const uint32_t aB = sb + 32768 + ch * 32768;
    const uint32_t kbA = (uint32_t)(k16 * 32 + c.achk);
    const uint32_t kbB = (uint32_t)(k16 * 32 + c.bchk);
#pragma unroll
    for (int mi = 0; mi < 4; mi++)
        ldsm4(av[mi], aA + swz((uint32_t)((c.arow + mi * 16) * 128) + kbA));
#pragma unroll
    for (int nj2 = 0; nj2 < 4; nj2++) {
        uint32_t t[4];
        ldsm4(t, aB + swz((uint32_t)((c.brow + nj2 * 16) * 128) + kbB));
        bv[nj2*2][0] = t[0]; bv[nj2*2][1] = t[1];
        bv[nj2*2+1][0] = t[2]; bv[nj2*2+1][1] = t[3];
    }
}

// ------------------------- fp32-acc tile -------------------------
// OUT: 0 fp32 -> Cf; 1 fp16 -> Ch. biasMode: 0 none, 1 per-col(n), 2 per-row(m).
template<int OUT>
__device__ __forceinline__ void gemm_tile(
    const __half* __restrict__ A, int lda,
    const __half* __restrict__ B, int ldb,
    float* __restrict__ Cf, __half* __restrict__ Ch, int ldc,
    int Kdim, float alpha, const float* __restrict__ bias, int biasMode,
    int m0, int n0, char* smem_raw)
{
    TileCtx c = tile_ctx(smem_raw);
    float acc[4][8][4];
#pragma unroll
    for (int i = 0; i < 4; i++)
#pragma unroll
        for (int j = 0; j < 8; j++)
#pragma unroll
            for (int r = 0; r < 4; r++) acc[i][j][r] = 0.f;

    const int NT = Kdim / BKE;
    load_stage_g(c, 0, 0, A, lda, B, ldb, m0, n0);
    for (int t = 0; t < NT; t++) {
        if (t + 1 < NT) { load_stage_g(c, (t + 1) & 1, (t + 1) * BKE, A, lda, B, ldb, m0, n0); cp_wait1(); }
        else            { cp_wait0(); }
        __syncthreads();
#pragma unroll
        for (int ch = 0; ch < 2; ch++)
#pragma unroll
            for (int k16 = 0; k16 < 4; k16++) {
                uint32_t av[4][4], bv[8][2];
                load_frags(c, t & 1, ch, k16, av, bv);
#pragma unroll
                for (int mi = 0; mi < 4; mi++)
#pragma unroll
                    for (int nj = 0; nj < 8; nj++)
                        mma_f32acc(acc[mi][nj], av[mi], bv[nj]);
            }
        __syncthreads();
    }

    const int gl = c.lane >> 2, q = c.lane & 3;
#pragma unroll
    for (int mi = 0; mi < 4; mi++)
#pragma unroll
        for (int nj = 0; nj < 8; nj++) {
            const int n = n0 + c.warp_n * 64 + nj * 8 + q * 2;
            float bcol0 = 0.f, bcol1 = 0.f;
            if (biasMode == 1) { bcol0 = bias[n]; bcol1 = bias[n + 1]; }
#pragma unroll
            for (int h = 0; h < 2; h++) {
                const int m = m0 + c.warp_m * 64 + mi * 16 + gl + h * 8;
                float v0 = acc[mi][nj][2 * h + 0] * alpha;
                float v1 = acc[mi][nj][2 * h + 1] * alpha;
                if (biasMode == 1) { v0 += bcol0; v1 += bcol1; }
                if (biasMode == 2) { float bb = bias[m]; v0 += bb; v1 += bb; }
                const size_t gidx = (size_t)m * ldc + n;
                if (OUT == 0)
                    *(float2*)(Cf + gidx) = make_float2(v0, v1);
                else
                    *(uint32_t*)(Ch + gidx) = pack_h2(__float2half(v0), __float2half(v1));
            }
        }
}

// ------------------------- fp16-acc tile (damped path only) -------------------------
// Always fp16 out. biasMode: 0 none, 1 per-col.
__device__ __forceinline__ void gemm_tile_h(
    const __half* __restrict__ A, int lda,
    const __half* __restrict__ B, int ldb,
    __half* __restrict__ Ch, int ldc,
    int Kdim, const float* __restrict__ bias, int biasMode,
    int m0, int n0, char* smem_raw)
{
    TileCtx c = tile_ctx(smem_raw);
    uint32_t acc[4][8][2];
#pragma unroll
    for (int i = 0; i < 4; i++)
#pragma unroll
        for (int j = 0; j < 8; j++) { acc[i][j][0] = 0u; acc[i][j][1] = 0u; }

    const int NT = Kdim / BKE;
    load_stage_g(c, 0, 0, A, lda, B, ldb, m0, n0);
    for (int t = 0; t < NT; t++) {
        if (t + 1 < NT) { load_stage_g(c, (t + 1) & 1, (t + 1) * BKE, A, lda, B, ldb, m0, n0); cp_wait1(); }
        else            { cp_wait0(); }
        __syncthreads();
#pragma unroll
        for (int ch = 0; ch < 2; ch++)
#pragma unroll
            for (int k16 = 0; k16 < 4; k16++) {
                uint32_t av[4][4], bv[8][2];
                load_frags(c, t & 1, ch, k16, av, bv);
#pragma unroll
                for (int mi = 0; mi < 4; mi++)
#pragma unroll
                    for (int nj = 0; nj < 8; nj++)
                        mma_f16acc(acc[mi][nj], av[mi], bv[nj]);
            }
        __syncthreads();
    }

    const int gl = c.lane >> 2, q = c.lane & 3;
#pragma unroll
    for (int mi = 0; mi < 4; mi++)
#pragma unroll
        for (int nj = 0; nj < 8; nj++) {
            const int n = n0 + c.warp_n * 64 + nj * 8 + q * 2;
            float bcol0 = 0.f, bcol1 = 0.f;
            if (biasMode == 1) { bcol0 = bias[n]; bcol1 = bias[n + 1]; }
#pragma unroll
            for (int h = 0; h < 2; h++) {
                const int m = m0 + c.warp_m * 64 + mi * 16 + gl + h * 8;
                uint32_t packed = acc[mi][nj][h];
                if (biasMode == 1) {
                    __half2 hv = *(__half2*)&packed;
                    float v0 = __half2float(hv.x) + bcol0;
                    float v1 = __half2float(hv.y) + bcol1;
                    packed = pack_h2(__float2half(v0), __float2half(v1));
                }
                *(uint32_t*)(Ch + (size_t)m * ldc + n) = packed;
            }
        }
}

// ------------------------- merged Q|K|V projections (768 CTAs) -------------------------
// Q (z=0, weights prescaled by 1/32, fp16 acc), K (z=1, fp16 acc), V (z=2, fp32 acc).
__global__ void __launch_bounds__(NTHREADS, 1)
gemm_qkv(const __half* __restrict__ Xh, const __half* __restrict__ Wc,
         __half* __restrict__ QKVh, const float* __restrict__ bqkv)
{
    extern __shared__ char smem_raw[];
    const int id = blockIdx.x;
    const int z  = id >> 8;          // 0=Q, 1=K, 2=V
    const int r  = id & 255;         // 64m x 4n
    const int m0 = (r >> 2) * BM, n0 = (r & 3) * BN;
    __half* Cz = QKVh + (size_t)z * BS_ROWS * DMODEL;
    if (z < 2)
        gemm_tile_h(Xh, DMODEL, Wc + (size_t)z * WSZ, DMODEL,
                    Cz, DMODEL, DMODEL, bqkv + z * DMODEL, 1, m0, n0, smem_raw);
    else
        gemm_tile<1>(Xh, DMODEL, Wc + 2 * (size_t)WSZ, DMODEL,
                     nullptr, Cz, DMODEL, DMODEL, 1.f, bqkv + 2 * DMODEL, 1,
                     m0, n0, smem_raw);
}

// ------------------------- merged scores | W'^T (768 CTAs) -------------------------
// id<512: scores_z = Q'_z K_z^T (Q prescaled by 1/32) -> fp16, fp16 acc
// id>=512: W'^T = Wo @ V^T -> fp16, fp32 acc
__global__ void __launch_bounds__(NTHREADS, 1)
gemm_sw(const __half* __restrict__ QKVh, const __half* __restrict__ Wo,
        __half* __restrict__ Sh, __half* __restrict__ WpT)
{
    extern __shared__ char smem_raw[];
    const int id = blockIdx.x;
    const size_t PS = (size_t)BS_ROWS * DMODEL;
    if (id < 512) {
        const int z = id >> 7;
        const int r = id & 127;          // 16m x 8n
        gemm_tile_h(QKVh + (size_t)z * SEQ * DMODEL, DMODEL,
                    QKVh + PS + (size_t)z * SEQ * DMODEL, DMODEL,
                    Sh + (size_t)z * SEQ * SEQ, SEQ,
                    DMODEL, nullptr, 0,
                    (r >> 3) * BM, (r & 7) * BN, smem_raw);
    } else {
        const int vid = id - 512;        // 8m x 32n
        gemm_tile<1>(Wo, DMODEL, QKVh + 2 * PS, DMODEL,
                     nullptr, WpT, BS_ROWS,
                     DMODEL, 1.f, nullptr, 0,
                     (vid >> 5) * BM, (vid & 31) * BN, smem_raw);
    }
}

// ------------------------- final GEMM: out = P @ W' + bo (fp32) -------------------------
__global__ void __launch_bounds__(NTHREADS, 1)
gemm_out(const __half* __restrict__ Ph, const __half* __restrict__ WpT,
         float* __restrict__ out, const float* __restrict__ bo)
{
    extern __shared__ char smem_raw[];
    const int z = blockIdx.z;
    gemm_tile<0>(Ph + (size_t)z * SEQ * SEQ, SEQ,
                 WpT + (size_t)z * SEQ, BS_ROWS,
                 out + (size_t)z * SEQ * DMODEL, nullptr, DMODEL,
                 SEQ, 1.f, bo, 1,
                 blockIdx.y * BM, blockIdx.x * BN, smem_raw);
}

// ------------------------- fp32 -> fp16 converts -------------------------
__global__ void __launch_bounds__(256)
conv_f16(const float* __restrict__ x, __half* __restrict__ h, int n4)
{
    int i = blockIdx.x * blockDim.x + threadIdx.x;
    if (i >= n4) return;
    float4 t = ((const float4*)x)[i];
    uint2 hv;
    hv.x = pack_h2(__float2half(t.x), __float2half(t.y));
    hv.y = pack_h2(__float2half(t.z), __float2half(t.w));
    ((uint2*)h)[i] = hv;
}

// seg 0 (Wq) is prescaled by 1/32 so the scores GEMM needs no alpha.
__global__ void __launch_bounds__(256)
conv4_f16(const float* __restrict__ w0, const float* __restrict__ w1,
          const float* __restrict__ w2, const float* __restrict__ w3,
          __half* __restrict__ dst)
{
    const int seg = blockIdx.y;
    const float* s = (seg == 0) ? w0 : (seg == 1) ? w1 : (seg == 2) ? w2 : w3;
    const float sc = (seg == 0) ? 0.03125f : 1.f;
    int i = blockIdx.x * blockDim.x + threadIdx.x;
    if (i >= WSZ / 4) return;
    float4 t = ((const float4*)s)[i];
    uint2 hv;
    hv.x = pack_h2(__float2half(t.x * sc), __float2half(t.y * sc));
    hv.y = pack_h2(__float2half(t.z * sc), __float2half(t.w * sc));
    ((uint2*)(dst + (size_t)seg * WSZ))[i] = hv;
}

// ------------------------- pack Q/K/V biases (bq prescaled by 1/32) -------------------------
__global__ void __launch_bounds__(256)
pack_bias(const float* __restrict__ bq, const float* __restrict__ bk,
          const float* __restrict__ bv, float* __restrict__ dst)
{
    int i = blockIdx.x * blockDim.x + threadIdx.x;
    if (i < DMODEL)               dst[i] = bq[i] * 0.03125f;
    else if (i < 2 * DMODEL)      dst[i] = bk[i - DMODEL];
    else if (i < 3 * DMODEL)      dst[i] = bv[i - 2 * DMODEL];
}

// ------------------------- softmax + intensity (fp16 scores in) -> fp16 P -------------------------
__global__ void __launch_bounds__(256)
softmax_f16(const __half* __restrict__ S, const float* __restrict__ inten,
            __half* __restrict__ P)
{
    const size_t row = blockIdx.x;
    const __half* sr = S + row * SEQ;
    const float* ir = inten + row * SEQ;
    const int tid = threadIdx.x;
    const int base = tid * 8;

    uint4 sraw = *(const uint4*)(sr + base);
    float v[8];
    {
        const uint32_t* sw = (const uint32_t*)&sraw;
#pragma unroll
        for (int i = 0; i < 4; i++) {
            __half2 hh = *(const __half2*)&sw[i];
            v[2*i]   = __half2float(hh.x);
            v[2*i+1] = __half2float(hh.y);
        }
    }
    float mx = v[0];
#pragma unroll
    for (int i = 1; i < 8; i++) mx = fmaxf(mx, v[i]);
    __shared__ float red[8];
#pragma unroll
    for (int o = 16; o > 0; o >>= 1)
        mx = fmaxf(mx, __shfl_xor_sync(0xffffffffu, mx, o));
    if ((tid & 31) == 0) red[tid >> 5] = mx;
    __syncthreads();
    mx = red[0];
#pragma unroll
    for (int i = 1; i < 8; i++) mx = fmaxf(mx, red[i]);
    __syncthreads();

    float sum = 0.f;
#pragma unroll
    for (int i = 0; i < 8; i++) {
        v[i] = expf(v[i] - mx);
        sum += v[i];
    }
#pragma unroll
    for (int o = 16; o > 0; o >>= 1)
        sum += __shfl_xor_sync(0xffffffffu, sum, o);
    if ((tid & 31) == 0) red[tid >> 5] = sum;
    __syncthreads();
    sum = 0.f;
#pragma unroll
    for (int i = 0; i < 8; i++) sum += red[i];
    const float inv = 1.f / sum;

    float w[8];
    *(float4*)&w[0] = *(const float4*)(ir + base);
    *(float4*)&w[4] = *(const float4*)(ir + base + 4);

    uint4 out;
    out.x = pack_h2(__float2half(v[0]*inv + w[0]), __float2half(v[1]*inv + w[1]));
    out.y = pack_h2(__float2half(v[2]*inv + w[2]), __float2half(v[3]*inv + w[3]));
    out.z = pack_h2(__float2half(v[4]*inv + w[4]), __float2half(v[5]*inv + w[5]));
    out.w = pack_h2(__float2half(v[6]*inv + w[6]), __float2half(v[7]*inv + w[7]));
    *(uint4*)(P + row * SEQ + base) = out;
}

// ------------------------- launch -------------------------
extern "C" void kernel_launch(void* const* d_in, const int* in_sizes, int n_in,
                              void* d_out, int out_size)
{
    const float* X  = (const float*)d_in[0];
    const float* I  = (const float*)d_in[1];
    const float* Wq = (const float*)d_in[2];
    const float* bq = (const float*)d_in[3];
    const float* Wk = (const float*)d_in[4];
    const float* bk = (const float*)d_in[5];
    const float* Wv = (const float*)d_in[6];
    const float* bv = (const float*)d_in[7];
    const float* Wo = (const float*)d_in[8];
    const float* bo = (const float*)d_in[9];
    float* out = (float*)d_out;

    __half *Xh, *Wc, *QKVh, *WpT, *Ph, *Sh;
    float *bqkv;
    cudaGetSymbolAddress((void**)&Xh,   g_Xh);
    cudaGetSymbolAddress((void**)&Wc,   g_Wc);
    cudaGetSymbolAddress((void**)&QKVh, g_QKVh);
    cudaGetSymbolAddress((void**)&WpT,  g_WpT);
    cudaGetSymbolAddress((void**)&Ph,   g_Ph);
    cudaGetSymbolAddress((void**)&Sh,   g_Sh);
    cudaGetSymbolAddress((void**)&bqkv, g_bqkv);

    cudaFuncSetAttribute(gemm_qkv, cudaFuncAttributeMaxDynamicSharedMemorySize, SMEM_TOTAL);
    cudaFuncSetAttribute(gemm_sw,  cudaFuncAttributeMaxDynamicSharedMemorySize, SMEM_TOTAL);
    cudaFuncSetAttribute(gemm_out, cudaFuncAttributeMaxDynamicSharedMemorySize, SMEM_TOTAL);

    const int XN4 = BS_ROWS * DMODEL / 4;
    const int WN4 = WSZ / 4;

    // 1. convert inputs; pack biases (Wq, bq prescaled by 1/32)
    conv_f16<<<(XN4 + 255) / 256, 256>>>(X, Xh, XN4);
    conv4_f16<<<dim3((WN4 + 255) / 256, 4), 256>>>(Wq, Wk, Wv, Wo, Wc);
    pack_bias<<<(3 * DMODEL + 255) / 256, 256>>>(bq, bk, bv, bqkv);

    dim3 blk(NTHREADS);

    // 2. Q'|K|V projections (Q', K fp16-acc; V fp32-acc)
    gemm_qkv<<<768, blk, SMEM_TOTAL>>>(Xh, Wc, QKVh, bqkv);
    // 3. scores (fp16-acc) | W'^T (fp32-acc)
    gemm_sw<<<768, blk, SMEM_TOTAL>>>(QKVh, Wc + 3 * (size_t)WSZ, Sh, WpT);
    // 4. attn = softmax + intensity -> fp16
    softmax_f16<<<BATCH * SEQ, 256>>>(Sh, I, Ph);
    // 5. out = P @ W' + bo -> fp32 (fp32-acc)
    dim3 gO(DMODEL / BN, SEQ / BM, BATCH);   // (4, 16, 4)
    gemm_out<<<gO, blk, SMEM_TOTAL>>>(Ph, WpT, out, bo);
}

// round 17
// speedup vs baseline: 1.0018x; 1.0018x over previous
#include <cuda_runtime.h>
#include <cuda_fp16.h>
#include <cstdint>

#define BATCH 4
#define SEQ   2048
#define DMODEL 1024
#define BS_ROWS (BATCH*SEQ)   // 8192
#define WSZ (DMODEL*DMODEL)

#define BM 128
#define BN 256
#define BKE 128                // fp16 K elems per stage (2 x 128B chunks)
#define NTHREADS 256
#define STAGE_BYTES 98304      // A 32K (2x16K) + B 64K (2x32K)
#define SMEM_TOTAL (1024 + 2*STAGE_BYTES)

// ------------------------- scratch (device globals) -------------------------
__device__ __half g_Xh[BS_ROWS*DMODEL];
__device__ __half g_Wc[4*WSZ];                       // [Wq/32, Wk, Wv, Wo]
__device__ __half g_QKVh[3*(size_t)BS_ROWS*DMODEL];  // [Q/32, K, V] row-major
__device__ __half g_WpT[(size_t)DMODEL*BS_ROWS];     // Wo @ V^T
__device__ __half g_Ph[(size_t)BATCH*SEQ*SEQ];
__device__ __half g_Sh[(size_t)BATCH*SEQ*SEQ];       // scores, fp16
__device__ float  g_bqkv[3*DMODEL];                  // [bq/32, bk, bv]

// ------------------------- PTX helpers -------------------------
__device__ __forceinline__ uint32_t smem_u32(const void* p) {
    uint32_t a;
    asm("{ .reg .u64 t; cvta.to.shared.u64 t, %1; cvt.u32.u64 %0, t; }" : "=r"(a) : "l"(p));
    return a;
}
__device__ __forceinline__ uint32_t swz(uint32_t o) { return o ^ ((o >> 3) & 0x70); }

__device__ __forceinline__ void cp16(uint32_t s, const void* g) {
    asm volatile("cp.async.cg.shared.global [%0], [%1], 16;" :: "r"(s), "l"(g) : "memory");
}
__device__ __forceinline__ void cp_commit() { asm volatile("cp.async.commit_group;" ::: "memory"); }
__device__ __forceinline__ void cp_wait0()  { asm volatile("cp.async.wait_group 0;" ::: "memory"); }
__device__ __forceinline__ void cp_wait1()  { asm volatile("cp.async.wait_group 1;" ::: "memory"); }

__device__ __forceinline__ void ldsm4(uint32_t* r, uint32_t addr) {
    asm volatile("ldmatrix.sync.aligned.m8n8.x4.shared.b16 {%0,%1,%2,%3}, [%4];"
                 : "=r"(r[0]), "=r"(r[1]), "=r"(r[2]), "=r"(r[3]) : "r"(addr));
}
__device__ __forceinline__ void mma_f32acc(float* d, const uint32_t* a, const uint32_t* b) {
    asm volatile(
        "mma.sync.aligned.m16n8k16.row.col.f32.f16.f16.f32 "
        "{%0,%1,%2,%3}, {%4,%5,%6,%7}, {%8,%9}, {%0,%1,%2,%3};"
        : "+f"(d[0]), "+f"(d[1]), "+f"(d[2]), "+f"(d[3])
        : "r"(a[0]), "r"(a[1]), "r"(a[2]), "r"(a[3]), "r"(b[0]), "r"(b[1]));
}
__device__ __forceinline__ void mma_f16acc(uint32_t* d, const uint32_t* a, const uint32_t* b) {
    asm volatile(
        "mma.sync.aligned.m16n8k16.row.col.f16.f16.f16.f16 "
        "{%0,%1}, {%2,%3,%4,%5}, {%6,%7}, {%0,%1};"
        : "+r"(d[0]), "+r"(d[1])
        : "r"(a[0]), "r"(a[1]), "r"(a[2]), "r"(a[3]), "r"(b[0]), "r"(b[1]));
}
__device__ __forceinline__ uint32_t pack_h2(__half a, __half b) {
    __half2 p; p.x = a; p.y = b;
    return *(uint32_t*)&p;
}

// ======================= shared tile machinery =======================
struct TileCtx {
    uint32_t su;
    int tid, lane, warp_m, warp_n;
    int arow, achk, brow, bchk;
};
__device__ __forceinline__ TileCtx tile_ctx(char* smem_raw) {
    TileCtx c;
    c.su = (smem_u32(smem_raw) + 1023u) & ~1023u;
    c.tid = threadIdx.x;
    c.lane = c.tid & 31;
    int wid = c.tid >> 5;
    c.warp_m = wid >> 2;
    c.warp_n = wid & 3;
    c.arow = c.warp_m * 64 + (c.lane & 7) + ((c.lane >> 3) & 1) * 8;
    c.achk = (c.lane >> 4) * 16;
    c.brow = c.warp_n * 64 + (c.lane & 7) + ((c.lane >> 4) & 1) * 8;
    c.bchk = ((c.lane >> 3) & 1) * 16;
    return c;
}
__device__ __forceinline__ void load_stage_g(
    const TileCtx& c, int buf, int kt,
    const __half* __restrict__ A, int lda, const __half* __restrict__ B, int ldb,
    int m0, int n0)
{
    const uint32_t base = c.su + buf * STAGE_BYTES;
    const __half* gA = A + (size_t)m0 * lda + kt;
    const __half* gB = B + (size_t)n0 * ldb + kt;
#pragma unroll
    for (int ch = 0; ch < 2; ch++) {
#pragma unroll
        for (int i = 0; i < 4; i++) {
            int u = c.tid + i * NTHREADS;
            int r = u >> 3, eb = (u & 7) * 16;
            cp16(base + ch * 16384 + swz((uint32_t)(r * 128 + eb)),
                 gA + (size_t)r * lda + (eb >> 1) + ch * 64);
        }
#pragma unroll
        for (int i = 0; i < 8; i++) {
            int u = c.tid + i * NTHREADS;
            int r = u >> 3, eb = (u & 7) * 16;
            cp16(base + 32768 + ch * 32768 + swz((uint32_t)(r * 128 + eb)),
                 gB + (size_t)r * ldb + (eb >> 1) + ch * 64);
        }
    }
    cp_commit();
}
// load fragments for flat group g (= ch*4 + k16) of buffer buf
__device__ __forceinline__ void load_frags(
    const TileCtx& c, int buf, int g, uint32_t av[4][4], uint32_t bv[8][2])
{
    const int ch = g >> 2, k16 = g & 3;
    const uint32_t sb = c.su + buf * STAGE_BYTES;
    const uint32_t aA = sb + ch * 16384;
    const uint32_t aB = sb + 32768 + ch * 32768;
    const uint32_t kbA = (uint32_t)(k16 * 32 + c.achk);
    const uint32_t kbB = (uint32_t)(k16 * 32 + c.bchk);
#pragma unroll
    for (int mi = 0; mi < 4; mi++)
        ldsm4(av[mi], aA + swz((uint32_t)((c.arow + mi * 16) * 128) + kbA));
#pragma unroll
    for (int nj2 = 0; nj2 < 4; nj2++) {
        uint32_t t[4];
        ldsm4(t, aB + swz((uint32_t)((c.brow + nj2 * 16) * 128) + kbB));
        bv[nj2*2][0] = t[0]; bv[nj2*2][1] = t[1];
        bv[nj2*2+1][0] = t[2]; bv[nj2*2+1][1] = t[3];
    }
}

// ------------------------- fp32-acc tile (unchanged; no reg headroom) -------------------------
// OUT: 0 fp32 -> Cf; 1 fp16 -> Ch. biasMode: 0 none, 1 per-col(n), 2 per-row(m).
template<int OUT>
__device__ __forceinline__ void gemm_tile(
    const __half* __restrict__ A, int lda,
    const __half* __restrict__ B, int ldb,
    float* __restrict__ Cf, __half* __restrict__ Ch, int ldc,
    int Kdim, float alpha, const float* __restrict__ bias, int biasMode,
    int m0, int n0, char* smem_raw)
{
    TileCtx c = tile_ctx(smem_raw);
    float acc[4][8][4];
#pragma unroll
    for (int i = 0; i < 4; i++)
#pragma unroll
        for (int j = 0; j < 8; j++)
#pragma unroll
            for (int r = 0; r < 4; r++) acc[i][j][r] = 0.f;

    const int NT = Kdim / BKE;
    load_stage_g(c, 0, 0, A, lda, B, ldb, m0, n0);
    for (int t = 0; t < NT; t++) {
        if (t + 1 < NT) { load_stage_g(c, (t + 1) & 1, (t + 1) * BKE, A, lda, B, ldb, m0, n0); cp_wait1(); }
        else            { cp_wait0(); }
        __syncthreads();
#pragma unroll
        for (int g = 0; g < 8; g++) {
            uint32_t av[4][4], bv[8][2];
            load_frags(c, t & 1, g, av, bv);
#pragma unroll
            for (int mi = 0; mi < 4; mi++)
#pragma unroll
                for (int nj = 0; nj < 8; nj++)
                    mma_f32acc(acc[mi][nj], av[mi], bv[nj]);
        }
        __syncthreads();
    }

    const int gl = c.lane >> 2, q = c.lane & 3;
#pragma unroll
    for (int mi = 0; mi < 4; mi++)
#pragma unroll
        for (int nj = 0; nj < 8; nj++) {
            const int n = n0 + c.warp_n * 64 + nj * 8 + q * 2;
            float bcol0 = 0.f, bcol1 = 0.f;
            if (biasMode == 1) { bcol0 = bias[n]; bcol1 = bias[n + 1]; }
#pragma unroll
            for (int h = 0; h < 2; h++) {
                const int m = m0 + c.warp_m * 64 + mi * 16 + gl + h * 8;
                float v0 = acc[mi][nj][2 * h + 0] * alpha;
                float v1 = acc[mi][nj][2 * h + 1] * alpha;
                if (biasMode == 1) { v0 += bcol0; v1 += bcol1; }
                if (biasMode == 2) { float bb = bias[m]; v0 += bb; v1 += bb; }
                const size_t gidx = (size_t)m * ldc + n;
                if (OUT == 0)
                    *(float2*)(Cf + gidx) = make_float2(v0, v1);
                else
                    *(uint32_t*)(Ch + gidx) = pack_h2(__float2half(v0), __float2half(v1));
            }
        }
}

// ------------------------- fp16-acc tile with k16 fragment pipelining -------------------------
// Damped path only (Q', K, scores). fp16 out. biasMode: 0 none, 1 per-col.
// acc = 64 regs (fp16) frees room for double-buffered fragments: MMAs of group g
// overlap the LDSM of group g+1, removing the per-group RAW stall.
__device__ __forceinline__ void gemm_tile_h(
    const __half* __restrict__ A, int lda,
    const __half* __restrict__ B, int ldb,
    __half* __restrict__ Ch, int ldc,
    int Kdim, const float* __restrict__ bias, int biasMode,
    int m0, int n0, char* smem_raw)
{
    TileCtx c = tile_ctx(smem_raw);
    uint32_t acc[4][8][2];
#pragma unroll
    for (int i = 0; i < 4; i++)
#pragma unroll
        for (int j = 0; j < 8; j++) { acc[i][j][0] = 0u; acc[i][j][1] = 0u; }

    uint32_t av[2][4][4], bv[2][8][2];   // double-buffered fragments

    const int NT = Kdim / BKE;
    load_stage_g(c, 0, 0, A, lda, B, ldb, m0, n0);
    for (int t = 0; t < NT; t++) {
        if (t + 1 < NT) { load_stage_g(c, (t + 1) & 1, (t + 1) * BKE, A, lda, B, ldb, m0, n0); cp_wait1(); }
        else            { cp_wait0(); }
        __syncthreads();
        load_frags(c, t & 1, 0, av[0], bv[0]);
#pragma unroll
        for (int g = 0; g < 8; g++) {
            const int cur = g & 1;
            if (g + 1 < 8) load_frags(c, t & 1, g + 1, av[cur ^ 1], bv[cur ^ 1]);
#pragma unroll
            for (int mi = 0; mi < 4; mi++)
#pragma unroll
                for (int nj = 0; nj < 8; nj++)
                    mma_f16acc(acc[mi][nj], av[cur][mi], bv[cur][nj]);
        }
        __syncthreads();
    }

    const int gl = c.lane >> 2, q = c.lane & 3;
#pragma unroll
    for (int mi = 0; mi < 4; mi++)
#pragma unroll
        for (int nj = 0; nj < 8; nj++) {
            const int n = n0 + c.warp_n * 64 + nj * 8 + q * 2;
            float bcol0 = 0.f, bcol1 = 0.f;
            if (biasMode == 1) { bcol0 = bias[n]; bcol1 = bias[n + 1]; }
#pragma unroll
            for (int h = 0; h < 2; h++) {
                const int m = m0 + c.warp_m * 64 + mi * 16 + gl + h * 8;
                uint32_t packed = acc[mi][nj][h];
                if (biasMode == 1) {
                    __half2 hv = *(__half2*)&packed;
                    float v0 = __half2float(hv.x) + bcol0;
                    float v1 = __half2float(hv.y) + bcol1;
                    packed = pack_h2(__float2half(v0), __float2half(v1));
                }
                *(uint32_t*)(Ch + (size_t)m * ldc + n) = packed;
            }
        }
}

// ------------------------- merged Q|K|V projections (768 CTAs) -------------------------
// Q (z=0, weights prescaled by 1/32, fp16 acc), K (z=1, fp16 acc), V (z=2, fp32 acc).
__global__ void __launch_bounds__(NTHREADS, 1)
gemm_qkv(const __half* __restrict__ Xh, const __half* __restrict__ Wc,
         __half* __restrict__ QKVh, const float* __restrict__ bqkv)
{
    extern __shared__ char smem_raw[];
    const int id = blockIdx.x;
    const int z  = id >> 8;          // 0=Q, 1=K, 2=V
    const int r  = id & 255;         // 64m x 4n
    const int m0 = (r >> 2) * BM, n0 = (r & 3) * BN;
    __half* Cz = QKVh + (size_t)z * BS_ROWS * DMODEL;
    if (z < 2)
        gemm_tile_h(Xh, DMODEL, Wc + (size_t)z * WSZ, DMODEL,
                    Cz, DMODEL, DMODEL, bqkv + z * DMODEL, 1, m0, n0, smem_raw);
    else
        gemm_tile<1>(Xh, DMODEL, Wc + 2 * (size_t)WSZ, DMODEL,
                     nullptr, Cz, DMODEL, DMODEL, 1.f, bqkv + 2 * DMODEL, 1,
                     m0, n0, smem_raw);
}

// ------------------------- merged scores | W'^T (768 CTAs) -------------------------
// id<512: scores_z = Q'_z K_z^T (Q prescaled by 1/32) -> fp16, fp16 acc pipelined
// id>=512: W'^T = Wo @ V^T -> fp16, fp32 acc
__global__ void __launch_bounds__(NTHREADS, 1)
gemm_sw(const __half* __restrict__ QKVh, const __half* __restrict__ Wo,
        __half* __restrict__ Sh, __half* __restrict__ WpT)
{
    extern __shared__ char smem_raw[];
    const int id = blockIdx.x;
    const size_t PS = (size_t)BS_ROWS * DMODEL;
    if (id < 512) {
        const int z = id >> 7;
        const int r = id & 127;          // 16m x 8n
        gemm_tile_h(QKVh + (size_t)z * SEQ * DMODEL, DMODEL,
                    QKVh + PS + (size_t)z * SEQ * DMODEL, DMODEL,
                    Sh + (size_t)z * SEQ * SEQ, SEQ,
                    DMODEL, nullptr, 0,
                    (r >> 3) * BM, (r & 7) * BN, smem_raw);
    } else {
        const int vid = id - 512;        // 8m x 32n
        gemm_tile<1>(Wo, DMODEL, QKVh + 2 * PS, DMODEL,
                     nullptr, WpT, BS_ROWS,
                     DMODEL, 1.f, nullptr, 0,
                     (vid >> 5) * BM, (vid & 31) * BN, smem_raw);
    }
}

// ------------------------- final GEMM: out = P @ W' + bo (fp32) -------------------------
__global__ void __launch_bounds__(NTHREADS, 1)
gemm_out(const __half* __restrict__ Ph, const __half* __restrict__ WpT,
         float* __restrict__ out, const float* __restrict__ bo)
{
    extern __shared__ char smem_raw[];
    const int z = blockIdx.z;
    gemm_tile<0>(Ph + (size_t)z * SEQ * SEQ, SEQ,
                 WpT + (size_t)z * SEQ, BS_ROWS,
                 out + (size_t)z * SEQ * DMODEL, nullptr, DMODEL,
                 SEQ, 1.f, bo, 1,
                 blockIdx.y * BM, blockIdx.x * BN, smem_raw);
}

// ------------------------- fp32 -> fp16 converts -------------------------
__global__ void __launch_bounds__(256)
conv_f16(const float* __restrict__ x, __half* __restrict__ h, int n4)
{
    int i = blockIdx.x * blockDim.x + threadIdx.x;
    if (i >= n4) return;
    float4 t = ((const float4*)x)[i];
    uint2 hv;
    hv.x = pack_h2(__float2half(t.x), __float2half(t.y));
    hv.y = pack_h2(__float2half(t.z), __float2half(t.w));
    ((uint2*)h)[i] = hv;
}

// seg 0 (Wq) prescaled by 1/32 so the scores GEMM needs no alpha.
__global__ void __launch_bounds__(256)
conv4_f16(const float* __restrict__ w0, const float* __restrict__ w1,
          const float* __restrict__ w2, const float* __restrict__ w3,
          __half* __restrict__ dst)
{
    const int seg = blockIdx.y;
    const float* s = (seg == 0) ? w0 : (seg == 1) ? w1 : (seg == 2) ? w2 : w3;
    const float sc = (seg == 0) ? 0.03125f : 1.f;
    int i = blockIdx.x * blockDim.x + threadIdx.x;
    if (i >= WSZ / 4) return;
    float4 t = ((const float4*)s)[i];
    uint2 hv;
    hv.x = pack_h2(__float2half(t.x * sc), __float2half(t.y * sc));
    hv.y = pack_h2(__float2half(t.z * sc), __float2half(t.w * sc));
    ((uint2*)(dst + (size_t)seg * WSZ))[i] = hv;
}

// ------------------------- pack Q/K/V biases (bq prescaled by 1/32) -------------------------
__global__ void __launch_bounds__(256)
pack_bias(const float* __restrict__ bq, const float* __restrict__ bk,
          const float* __restrict__ bv, float* __restrict__ dst)
{
    int i = blockIdx.x * blockDim.x + threadIdx.x;
    if (i < DMODEL)               dst[i] = bq[i] * 0.03125f;
    else if (i < 2 * DMODEL)      dst[i] = bk[i - DMODEL];
    else if (i < 3 * DMODEL)      dst[i] = bv[i - 2 * DMODEL];
}

// ------------------------- softmax + intensity (fp16 scores in) -> fp16 P -------------------------
__global__ void __launch_bounds__(256)
softmax_f16(const __half* __restrict__ S, const float* __restrict__ inten,
            __half* __restrict__ P)
{
    const size_t row = blockIdx.x;
    const __half* sr = S + row * SEQ;
    const float* ir = inten + row * SEQ;
    const int tid = threadIdx.x;
    const int base = tid * 8;

    uint4 sraw = *(const uint4*)(sr + base);
    float v[8];
    {
        const uint32_t* sw = (const uint32_t*)&sraw;
#pragma unroll
        for (int i = 0; i < 4; i++) {
            __half2 hh = *(const __half2*)&sw[i];
            v[2*i]   = __half2float(hh.x);
            v[2*i+1] = __half2float(hh.y);
        }
    }
    float mx = v[0];
#pragma unroll
    for (int i = 1; i < 8; i++) mx = fmaxf(mx, v[i]);
    __shared__ float red[8];
#pragma unroll
    for (int o = 16; o > 0; o >>= 1)
        mx = fmaxf(mx, __shfl_xor_sync(0xffffffffu, mx, o));
    if ((tid & 31) == 0) red[tid >> 5] = mx;
    __syncthreads();
    mx = red[0];
#pragma unroll
    for (int i = 1; i < 8; i++) mx = fmaxf(mx, red[i]);
    __syncthreads();

    float sum = 0.f;
#pragma unroll
    for (int i = 0; i < 8; i++) {
        v[i] = expf(v[i] - mx);
        sum += v[i];
    }
#pragma unroll
    for (int o = 16; o > 0; o >>= 1)
        sum += __shfl_xor_sync(0xffffffffu, sum, o);
    if ((tid & 31) == 0) red[tid >> 5] = sum;
    __syncthreads();
    sum = 0.f;
#pragma unroll
    for (int i = 0; i < 8; i++) sum += red[i];
    const float inv = 1.f / sum;

    float w[8];
    *(float4*)&w[0] = *(const float4*)(ir + base);
    *(float4*)&w[4] = *(const float4*)(ir + base + 4);

    uint4 out;
    out.x = pack_h2(__float2half(v[0]*inv + w[0]), __float2half(v[1]*inv + w[1]));
    out.y = pack_h2(__float2half(v[2]*inv + w[2]), __float2half(v[3]*inv + w[3]));
    out.z = pack_h2(__float2half(v[4]*inv + w[4]), __float2half(v[5]*inv + w[5]));
    out.w = pack_h2(__float2half(v[6]*inv + w[6]), __float2half(v[7]*inv + w[7]));
    *(uint4*)(P + row * SEQ + base) = out;
}

// ------------------------- launch -------------------------
extern "C" void kernel_launch(void* const* d_in, const int* in_sizes, int n_in,
                              void* d_out, int out_size)
{
    const float* X  = (const float*)d_in[0];
    const float* I  = (const float*)d_in[1];
    const float* Wq = (const float*)d_in[2];
    const float* bq = (const float*)d_in[3];
    const float* Wk = (const float*)d_in[4];
    const float* bk = (const float*)d_in[5];
    const float* Wv = (const float*)d_in[6];
    const float* bv = (const float*)d_in[7];
    const float* Wo = (const float*)d_in[8];
    const float* bo = (const float*)d_in[9];
    float* out = (float*)d_out;

    __half *Xh, *Wc, *QKVh, *WpT, *Ph, *Sh;
    float *bqkv;
    cudaGetSymbolAddress((void**)&Xh,   g_Xh);
    cudaGetSymbolAddress((void**)&Wc,   g_Wc);
    cudaGetSymbolAddress((void**)&QKVh, g_QKVh);
    cudaGetSymbolAddress((void**)&WpT,  g_WpT);
    cudaGetSymbolAddress((void**)&Ph,   g_Ph);
    cudaGetSymbolAddress((void**)&Sh,   g_Sh);
    cudaGetSymbolAddress((void**)&bqkv, g_bqkv);

    cudaFuncSetAttribute(gemm_qkv, cudaFuncAttributeMaxDynamicSharedMemorySize, SMEM_TOTAL);
    cudaFuncSetAttribute(gemm_sw,  cudaFuncAttributeMaxDynamicSharedMemorySize, SMEM_TOTAL);
    cudaFuncSetAttribute(gemm_out, cudaFuncAttributeMaxDynamicSharedMemorySize, SMEM_TOTAL);

    const int XN4 = BS_ROWS * DMODEL / 4;
    const int WN4 = WSZ / 4;

    // 1. convert inputs; pack biases (Wq, bq prescaled by 1/32)
    conv_f16<<<(XN4 + 255) / 256, 256>>>(X, Xh, XN4);
    conv4_f16<<<dim3((WN4 + 255) / 256, 4), 256>>>(Wq, Wk, Wv, Wo, Wc);
    pack_bias<<<(3 * DMODEL + 255) / 256, 256>>>(bq, bk, bv, bqkv);

    dim3 blk(NTHREADS);

    // 2. Q'|K|V projections (Q', K fp16-acc pipelined; V fp32-acc)
    gemm_qkv<<<768, blk, SMEM_TOTAL>>>(Xh, Wc, QKVh, bqkv);
    // 3. scores (fp16-acc pipelined) | W'^T (fp32-acc)
    gemm_sw<<<768, blk, SMEM_TOTAL>>>(QKVh, Wc + 3 * (size_t)WSZ, Sh, WpT);
    // 4. attn = softmax + intensity -> fp16
    softmax_f16<<<BATCH * SEQ, 256>>>(Sh, I, Ph);
    // 5. out = P @ W' + bo -> fp32 (fp32-acc)
    dim3 gO(DMODEL / BN, SEQ / BM, BATCH);   // (4, 16, 4)
    gemm_out<<<gO, blk, SMEM_TOTAL>>>(Ph, WpT, out, bo);
}